// round 13
// baseline (speedup 1.0000x reference)
#include <cuda_runtime.h>
#include <cstdint>
#include <math.h>

// Problem constants
#define Bv   4
#define Lv   1024
#define Dv   1024
#define Pv   2048
#define MBL  4096

// ---------------- scratch (device globals) ----------------
__device__ float g_r   [(size_t)Pv  * Dv];    // rel-pos table [P, D]
__device__ float g_hqu [(size_t)MBL * Dv];    // hq + u_w
__device__ float g_hqv [(size_t)MBL * Dv];    // hq + v_w
__device__ float g_hk  [(size_t)MBL * Dv];    // hk
__device__ float g_hvT [(size_t)Dv  * MBL];   // hv transposed: [H*64][B*L]
__device__ float g_hr  [(size_t)Pv  * Dv];    // hr [P][H*64]
__device__ float g_pos [(size_t)64 * Lv * Pv];// position scores (banded fill)
__device__ float g_cat [(size_t)MBL * Dv];    // concatenated heads

// ================= helpers =================
__device__ __forceinline__ uint32_t smem_u32(const void* p) {
    uint32_t a;
    asm("{ .reg .u64 t; cvta.to.shared.u64 t, %1; cvt.u32.u64 %0, t; }" : "=r"(a) : "l"(p));
    return a;
}
__device__ __forceinline__ void cpasync16(uint32_t dst, const float* src) {
    asm volatile("cp.async.cg.shared.global [%0], [%1], 16;" :: "r"(dst), "l"(src) : "memory");
}
__device__ __forceinline__ void cp_commit() { asm volatile("cp.async.commit_group;" ::: "memory"); }
template <int N> __device__ __forceinline__ void cp_wait() {
    asm volatile("cp.async.wait_group %0;" :: "n"(N) : "memory");
}
__device__ __forceinline__ uint32_t cvt_tf32(float x) {
    uint32_t r; asm("cvt.rna.tf32.f32 %0, %1;" : "=r"(r) : "f"(x)); return r;
}
__device__ __forceinline__ void mma8(float* c, const uint32_t* a, const uint32_t* b) {
    asm volatile("mma.sync.aligned.m16n8k8.row.col.f32.tf32.tf32.f32 "
        "{%0,%1,%2,%3}, {%4,%5,%6,%7}, {%8,%9}, {%0,%1,%2,%3};"
        : "+f"(c[0]), "+f"(c[1]), "+f"(c[2]), "+f"(c[3])
        : "r"(a[0]), "r"(a[1]), "r"(a[2]), "r"(a[3]), "r"(b[0]), "r"(b[1]));
}
__device__ __forceinline__ void ldsm4(uint32_t* r, uint32_t addr) {
    asm volatile("ldmatrix.sync.aligned.m8n8.x4.shared.b16 {%0,%1,%2,%3}, [%4];"
        : "=r"(r[0]), "=r"(r[1]), "=r"(r[2]), "=r"(r[3]) : "r"(addr));
}

// ================= generic tf32 warp-MMA GEMM (3-stage pipeline, ldmatrix) =================
// C[z][m][n] = sum_k A[..m,k] * B[..n,k]; B always [n][k] rows in smem (NK layout).
// EPI: 0 plain, 1 dual write +uvec/+vvec, 2 transposed write via smem stage,
//      3 residual add.
// XM:  1 = raw truncation; 3 = full 3xTF32 (logit-critical chains).
// Triple-buffered: ONE __syncthreads per 32-K chunk; prefetch issued right
// after the sync so each load has ~2 chunks of compute to hide behind.
template <int N_TILE, int EPI, int XM>
__global__ void __launch_bounds__(256, 1) gemm_mma(
    const float* __restrict__ A, int lda, long long a_bs, long long a_hs,
    const float* __restrict__ B, int ldb, long long b_bs, long long b_hs,
    float* __restrict__ C, float* __restrict__ C2, int ldc, long long c_bs, long long c_hs,
    const float* __restrict__ res, const float* __restrict__ uvec, const float* __restrict__ vvec,
    int K, int band)
{
    constexpr int WARPS_M = (N_TILE == 128) ? 2 : 4;
    constexpr int WM = 128 / WARPS_M;
    constexpr int WN = N_TILE / (8 / WARPS_M);
    constexpr int MF = WM / 16;
    constexpr int NF = WN / 8;
    constexpr int AS = 36;                 // smem row stride in floats (144B)
    constexpr int BS = 36;
    constexpr int A_FL = 128 * AS;
    constexpr int B_FL = N_TILE * BS;
    constexpr int STAGE = A_FL + B_FL;

    extern __shared__ float sh[];
    const uint32_t shu = smem_u32(sh);
    uint32_t Au[3], Bu[3];
#pragma unroll
    for (int s = 0; s < 3; s++) {
        Au[s] = shu + (uint32_t)(s * STAGE) * 4u;
        Bu[s] = shu + (uint32_t)(s * STAGE + A_FL) * 4u;
    }

    const int tid = threadIdx.x;
    const int wid = tid >> 5;
    const int lane = tid & 31;
    const int g  = lane >> 2;
    const int t4 = lane & 3;
    const int wm = wid % WARPS_M;
    const int wn = wid / WARPS_M;

    const int z = blockIdx.z, zb = z >> 4, zh = z & 15;
    const int m0 = blockIdx.x * 128;
    const int n0 = blockIdx.y * N_TILE + (band ? (896 - m0) : 0);
    const float* Abase = A + (size_t)zb * a_bs + (size_t)zh * a_hs + (size_t)m0 * lda;
    const float* Bbase = B + (size_t)zb * b_bs + (size_t)zh * b_hs + (size_t)n0 * ldb;
    const size_t coff = (size_t)zb * c_bs + (size_t)zh * c_hs;

    const int lane7 = lane & 7;
    const uint32_t a_lm = ((uint32_t)(wm * WM + lane7 + (((lane >> 3) & 1) << 3)) * AS
                           + ((lane & 16) ? 4u : 0u)) * 4u;
    const uint32_t b_lm = ((uint32_t)(wn * WN + lane7 + ((lane & 16) ? 8u : 0u)) * BS
                           + ((lane & 8) ? 4u : 0u)) * 4u;

    auto load_chunk = [&](int k0, int buf) {
        uint32_t sA = Au[buf], sB = Bu[buf];
#pragma unroll
        for (int s = tid; s < 1024; s += 256) {
            int r = s >> 3, c = s & 7;
            cpasync16(sA + (uint32_t)(r * (AS * 4) + c * 16), Abase + (size_t)r * lda + k0 + c * 4);
        }
#pragma unroll
        for (int s = tid; s < N_TILE * 8; s += 256) {
            int r = s >> 3, c = s & 7;
            cpasync16(sB + (uint32_t)(r * (BS * 4) + c * 16), Bbase + (size_t)r * ldb + k0 + c * 4);
        }
        cp_commit();
    };

    float acc[MF][NF][4] = {};

    const int NK = K >> 5;
    load_chunk(0, 0);
    if (NK > 1) load_chunk(32, 1);

    for (int kt = 0; kt < NK; kt++) {
        if (kt + 1 < NK) cp_wait<1>(); else cp_wait<0>();
        __syncthreads();          // chunk kt resident; compute(kt-1) retired in all warps
        if (kt + 2 < NK)          // buffer (kt+2)%3 was freed by the sync above
            load_chunk((kt + 2) << 5, (kt + 2) % 3);

        const uint32_t As_ = Au[kt % 3] + a_lm;
        const uint32_t Bs_ = Bu[kt % 3] + b_lm;
#pragma unroll
        for (int kk = 0; kk < 4; kk++) {
            uint32_t ah[MF][4], al[MF][4];
            uint32_t bh[NF][2], bl[NF][2];
#pragma unroll
            for (int mf = 0; mf < MF; mf++) {
                uint32_t raw[4];
                ldsm4(raw, As_ + (uint32_t)(mf * 16 * AS * 4) + (uint32_t)(kk * 32));
#pragma unroll
                for (int r = 0; r < 4; r++) {
                    if constexpr (XM >= 2) {
                        float x = __uint_as_float(raw[r]);
                        ah[mf][r] = cvt_tf32(x);
                        al[mf][r] = __float_as_uint(x - __uint_as_float(ah[mf][r]));
                    } else {
                        ah[mf][r] = raw[r];   // HW truncates f32 -> tf32
                    }
                }
            }
#pragma unroll
            for (int nfp = 0; nfp < NF / 2; nfp++) {
                uint32_t raw[4];
                ldsm4(raw, Bs_ + (uint32_t)(nfp * 16 * BS * 4) + (uint32_t)(kk * 32));
#pragma unroll
                for (int r = 0; r < 4; r++) {
                    int nf = 2 * nfp + (r >> 1), rr = r & 1;
                    if constexpr (XM == 3) {
                        float y = __uint_as_float(raw[r]);
                        bh[nf][rr] = cvt_tf32(y);
                        bl[nf][rr] = __float_as_uint(y - __uint_as_float(bh[nf][rr]));
                    } else {
                        bh[nf][rr] = raw[r];
                    }
                }
            }
#pragma unroll
            for (int mf = 0; mf < MF; mf++)
#pragma unroll
                for (int nf = 0; nf < NF; nf++) {
                    if constexpr (XM == 3) {
                        mma8(acc[mf][nf], al[mf], bh[nf]);
                        mma8(acc[mf][nf], ah[mf], bl[nf]);
                    }
                    mma8(acc[mf][nf], ah[mf], bh[nf]);
                }
        }
        // no trailing sync: next iteration's top sync provides the WAR guard
    }

    // ---------------- epilogue ----------------
    if constexpr (EPI == 2) {
        __syncthreads();          // all warps done reading smem buffers
        float* st = sh;
#pragma unroll
        for (int mf = 0; mf < MF; mf++)
#pragma unroll
            for (int nf = 0; nf < NF; nf++) {
                const float* a = acc[mf][nf];
                int rl = wm * WM + mf * 16 + g;
                int cl = wn * WN + nf * 8 + 2 * t4;
                st[(size_t)cl * 132 + rl]           = a[0];
                st[(size_t)(cl + 1) * 132 + rl]     = a[1];
                st[(size_t)cl * 132 + rl + 8]       = a[2];
                st[(size_t)(cl + 1) * 132 + rl + 8] = a[3];
            }
        __syncthreads();
        for (int s = tid; s < 128 * 32; s += 256) {
            int dv = s >> 5, c4 = (s & 31) << 2;
            float4 val = *(float4*)&st[(size_t)dv * 132 + c4];
            *(float4*)(C + (size_t)(n0 + dv) * ldc + m0 + c4) = val;
        }
        return;
    }
#pragma unroll
    for (int mf = 0; mf < MF; mf++) {
#pragma unroll
        for (int nf = 0; nf < NF; nf++) {
            const float* a = acc[mf][nf];
            const int row = m0 + wm * WM + mf * 16 + g;
            const int col = n0 + wn * WN + nf * 8 + 2 * t4;
            if constexpr (EPI == 0) {
                *(float2*)(C + coff + (size_t)row * ldc + col)       = make_float2(a[0], a[1]);
                *(float2*)(C + coff + (size_t)(row + 8) * ldc + col) = make_float2(a[2], a[3]);
            } else if constexpr (EPI == 1) {
                const int bi = col & 63;
                const float u0 = uvec[bi], u1 = uvec[bi + 1];
                const float v0 = vvec[bi], v1 = vvec[bi + 1];
                const size_t o1 = coff + (size_t)row * ldc + col;
                const size_t o2 = coff + (size_t)(row + 8) * ldc + col;
                *(float2*)(C  + o1) = make_float2(a[0] + u0, a[1] + u1);
                *(float2*)(C  + o2) = make_float2(a[2] + u0, a[3] + u1);
                *(float2*)(C2 + o1) = make_float2(a[0] + v0, a[1] + v1);
                *(float2*)(C2 + o2) = make_float2(a[2] + v0, a[3] + v1);
            } else {  // EPI == 3
                const size_t o1 = (size_t)row * ldc + col;
                const size_t o2 = (size_t)(row + 8) * ldc + col;
                float2 r1 = *(const float2*)(res + o1);
                float2 r2 = *(const float2*)(res + o2);
                *(float2*)(C + o1) = make_float2(a[0] + r1.x, a[1] + r1.y);
                *(float2*)(C + o2) = make_float2(a[2] + r2.x, a[3] + r2.y);
            }
        }
    }
}

// ================= flash kernel (256 threads): content X2 MMA + shift + online softmax + P@V ===
// smem (floats): sQ(hi)@0 128x68 | sK@8704 128x68 | sV@17408 64x132 | sP@25856 128x132
//   stats@42752 (m,s,f 128 each + red 512 + red2 512) | sQlo@44160 128x68
__global__ void __launch_bounds__(256, 1) flash_kernel(
    const float* __restrict__ hqu, const float* __restrict__ hk,
    const float* __restrict__ hvT, const float* __restrict__ pos,
    float* __restrict__ cat)
{
    extern __shared__ float sh[];
    float* sP    = sh + 25856;
    float* m_row = sh + 42752;
    float* s_row = m_row + 128;
    float* f_row = s_row + 128;
    float* red   = f_row + 128;
    float* red2  = red + 512;
    float* sQ    = sh;
    float* sQlo  = sh + 44160;

    const uint32_t shu = smem_u32(sh);
    const uint32_t uQ   = shu;
    const uint32_t uK   = shu + 8704u * 4u;
    const uint32_t uV   = shu + 17408u * 4u;
    const uint32_t uP   = shu + 25856u * 4u;
    const uint32_t uQlo = shu + 44160u * 4u;

    const int tid = threadIdx.x, wid = tid >> 5, lane = tid & 31;
    const int g = lane >> 2, t4 = lane & 3, lane7 = lane & 7;
    const int wm = wid >> 2, wn = wid & 3;     // S-MMA layout 2x4 (WM=64, WN=32)
    const int wm2 = wid & 3, wn2 = wid >> 2;   // O-MMA layout 4x2 (WM=32, WN=32)

    const int i0 = blockIdx.x * 128;
    const int z = blockIdx.y, zb = z >> 4, zh = z & 15;

    const float* Qg = hqu + (size_t)zb * 1048576 + (size_t)zh * 64 + (size_t)i0 * 1024;
    const float* Kg = hk  + (size_t)zb * 1048576 + (size_t)zh * 64;
    const float* Vg = hvT + (size_t)zb * 1024    + (size_t)zh * 262144;
    const float* Pg = pos + (size_t)zb * 33554432 + (size_t)zh * 2097152;

    for (int r = tid; r < 128; r += 256) { m_row[r] = -3.4e38f; s_row[r] = 0.f; }

    // preload: group1 = Q + K(0); group2 = V(0)
#pragma unroll
    for (int s = tid; s < 2048; s += 256) { int r = s >> 4, c = s & 15;
        cpasync16(uQ + (uint32_t)(r * 272 + c * 16), Qg + (size_t)r * 1024 + c * 4); }
#pragma unroll
    for (int s = tid; s < 2048; s += 256) { int r = s >> 4, c = s & 15;
        cpasync16(uK + (uint32_t)(r * 272 + c * 16), Kg + (size_t)r * 1024 + c * 4); }
    cp_commit();
#pragma unroll
    for (int s = tid; s < 2048; s += 256) { int r = s >> 5, c = s & 31;
        cpasync16(uV + (uint32_t)(r * 528 + c * 16), Vg + (size_t)r * 4096 + c * 4); }
    cp_commit();

    const uint32_t a_lmS = (uint32_t)(wm * 64 + lane7 + (((lane >> 3) & 1) << 3)) * 272u + ((lane & 16) ? 16u : 0u);
    const uint32_t b_lmS = (uint32_t)(wn * 32 + lane7 + ((lane & 16) ? 8 : 0)) * 272u + ((lane & 8) ? 16u : 0u);
    const uint32_t a_lmP = (uint32_t)(wm2 * 32 + lane7 + (((lane >> 3) & 1) << 3)) * 528u + ((lane & 16) ? 16u : 0u);
    const uint32_t b_lmV = (uint32_t)(wn2 * 32 + lane7 + ((lane & 16) ? 8 : 0)) * 528u + ((lane & 8) ? 16u : 0u);

    // ---- Q arrived (group1): split hi/lo once (reused by all 8 j-tiles) ----
    cp_wait<1>();
    __syncthreads();
#pragma unroll
    for (int s = tid; s < 8192; s += 256) {
        int r = s >> 6, c = s & 63;
        int idx = r * 68 + c;
        float x = sQ[idx];
        uint32_t hi = cvt_tf32(x);
        sQ[idx]   = __uint_as_float(hi);
        sQlo[idx] = x - __uint_as_float(hi);
    }
    __syncthreads();

    float oacc[2][4][4] = {};

    for (int jt = 0; jt < 8; jt++) {
        const int j0 = jt * 128;
        cp_wait<1>(); __syncthreads();           // K(jt) ready (no-op at jt=0)

        // ---- S = hqu_tile @ hk_tile^T (X2 tf32, K=64; A pre-split, K hi only) ----
        float sacc[4][4][4] = {};
#pragma unroll
        for (int kk = 0; kk < 8; kk++) {
            uint32_t ah[4][4], al[4][4], bh[4][2];
#pragma unroll
            for (int mf = 0; mf < 4; mf++) {
                ldsm4(ah[mf], uQ   + a_lmS + (uint32_t)(mf * 16 * 272) + (uint32_t)(kk * 32));
                ldsm4(al[mf], uQlo + a_lmS + (uint32_t)(mf * 16 * 272) + (uint32_t)(kk * 32));
            }
#pragma unroll
            for (int nfp = 0; nfp < 2; nfp++) {
                uint32_t raw[4];
                ldsm4(raw, uK + b_lmS + (uint32_t)(nfp * 16 * 272) + (uint32_t)(kk * 32));
#pragma unroll
                for (int r = 0; r < 4; r++) {
                    float y = __uint_as_float(raw[r]);
                    int nf = 2 * nfp + (r >> 1), rr = r & 1;
                    bh[nf][rr] = cvt_tf32(y);
                }
            }
#pragma unroll
            for (int mf = 0; mf < 4; mf++)
#pragma unroll
                for (int nf = 0; nf < 4; nf++) {
                    mma8(sacc[mf][nf], al[mf], bh[nf]);
                    mma8(sacc[mf][nf], ah[mf], bh[nf]);
                }
        }

        // ---- logits = (S + pos[i][1024-i+j]) / 32 ----
#pragma unroll
        for (int mf = 0; mf < 4; mf++) {
            const int r1 = i0 + wm * 64 + mf * 16 + g;
            const int r2 = r1 + 8;
            const float* pr1 = Pg + (size_t)r1 * 2048 + (1024 - r1 + j0);
            const float* pr2 = Pg + (size_t)r2 * 2048 + (1024 - r2 + j0);
#pragma unroll
            for (int nf = 0; nf < 4; nf++) {
                const int cj = wn * 32 + nf * 8 + 2 * t4;
                sacc[mf][nf][0] = (sacc[mf][nf][0] + pr1[cj])     * 0.03125f;
                sacc[mf][nf][1] = (sacc[mf][nf][1] + pr1[cj + 1]) * 0.03125f;
                sacc[mf][nf][2] = (sacc[mf][nf][2] + pr2[cj])     * 0.03125f;
                sacc[mf][nf][3] = (sacc[mf][nf][3] + pr2[cj + 1]) * 0.03125f;
            }
        }

        // ---- row max (local -> quad -> smem partials) ----
        float m_prev[8], mloc[8];
#pragma unroll
        for (int mf = 0; mf < 4; mf++)
#pragma unroll
            for (int h = 0; h < 2; h++) {
                int idx = mf * 2 + h;
                float mv = -3.4e38f;
#pragma unroll
                for (int nf = 0; nf < 4; nf++)
                    mv = fmaxf(mv, fmaxf(sacc[mf][nf][2 * h], sacc[mf][nf][2 * h + 1]));
                mloc[idx] = mv;
                m_prev[idx] = m_row[wm * 64 + mf * 16 + h * 8 + g];
            }
#pragma unroll
        for (int idx = 0; idx < 8; idx++) {
            mloc[idx] = fmaxf(mloc[idx], __shfl_xor_sync(0xffffffffu, mloc[idx], 1));
            mloc[idx] = fmaxf(mloc[idx], __shfl_xor_sync(0xffffffffu, mloc[idx], 2));
        }
        if (t4 == 0) {
#pragma unroll
            for (int mf = 0; mf < 4; mf++)
#pragma unroll
                for (int h = 0; h < 2; h++)
                    red[(wm * 64 + mf * 16 + h * 8 + g) * 4 + wn] = mloc[mf * 2 + h];
        }
        __syncthreads();                          // sync1: K reads done too

        if (jt < 7) {                             // prefetch K(jt+1), overlaps softmax+PV
            const float* Kn = Kg + (size_t)(j0 + 128) * 1024;
#pragma unroll
            for (int s = tid; s < 2048; s += 256) { int r = s >> 4, c = s & 15;
                cpasync16(uK + (uint32_t)(r * 272 + c * 16), Kn + (size_t)r * 1024 + c * 4); }
            cp_commit();
        }

        // ---- m_new, P = exp(logit - m_new), row sums ----
        float mn[8], fr[8], sl[8];
#pragma unroll
        for (int mf = 0; mf < 4; mf++)
#pragma unroll
            for (int h = 0; h < 2; h++) {
                int idx = mf * 2 + h;
                int row = wm * 64 + mf * 16 + h * 8 + g;
                float mm = fmaxf(fmaxf(red[row * 4 + 0], red[row * 4 + 1]),
                                 fmaxf(red[row * 4 + 2], red[row * 4 + 3]));
                mm = fmaxf(mm, m_prev[idx]);
                mn[idx] = mm;
                fr[idx] = expf(m_prev[idx] - mm);
                float ss = 0.f;
#pragma unroll
                for (int nf = 0; nf < 4; nf++) {
                    float p0 = expf(sacc[mf][nf][2 * h]     - mm);
                    float p1 = expf(sacc[mf][nf][2 * h + 1] - mm);
                    sacc[mf][nf][2 * h] = p0; sacc[mf][nf][2 * h + 1] = p1;
                    ss += p0 + p1;
                }
                sl[idx] = ss;
            }
#pragma unroll
        for (int idx = 0; idx < 8; idx++) {
            sl[idx] += __shfl_xor_sync(0xffffffffu, sl[idx], 1);
            sl[idx] += __shfl_xor_sync(0xffffffffu, sl[idx], 2);
        }
        if (t4 == 0) {
#pragma unroll
            for (int mf = 0; mf < 4; mf++)
#pragma unroll
                for (int h = 0; h < 2; h++) {
                    int row = wm * 64 + mf * 16 + h * 8 + g;
                    red2[row * 4 + wn] = sl[mf * 2 + h];
                    if (wn == 0) { m_row[row] = mn[mf * 2 + h]; f_row[row] = fr[mf * 2 + h]; }
                }
        }
        __syncthreads();                          // sync2

        if (wn == 0 && t4 == 0) {
#pragma unroll
            for (int mf = 0; mf < 4; mf++)
#pragma unroll
                for (int h = 0; h < 2; h++) {
                    int row = wm * 64 + mf * 16 + h * 8 + g;
                    s_row[row] = s_row[row] * fr[mf * 2 + h]
                        + red2[row * 4 + 0] + red2[row * 4 + 1] + red2[row * 4 + 2] + red2[row * 4 + 3];
                }
        }

        // ---- rescale O by f ----
#pragma unroll
        for (int mf2 = 0; mf2 < 2; mf2++) {
            float f1 = f_row[wm2 * 32 + mf2 * 16 + g];
            float f2 = f_row[wm2 * 32 + mf2 * 16 + g + 8];
#pragma unroll
            for (int nf2 = 0; nf2 < 4; nf2++) {
                oacc[mf2][nf2][0] *= f1; oacc[mf2][nf2][1] *= f1;
                oacc[mf2][nf2][2] *= f2; oacc[mf2][nf2][3] *= f2;
            }
        }

        // ---- stage P ----
#pragma unroll
        for (int mf = 0; mf < 4; mf++) {
            int r1 = wm * 64 + mf * 16 + g, r2 = r1 + 8;
#pragma unroll
            for (int nf = 0; nf < 4; nf++) {
                int cj = wn * 32 + nf * 8 + 2 * t4;
                sP[r1 * 132 + cj]     = sacc[mf][nf][0];
                sP[r1 * 132 + cj + 1] = sacc[mf][nf][1];
                sP[r2 * 132 + cj]     = sacc[mf][nf][2];
                sP[r2 * 132 + cj + 1] = sacc[mf][nf][3];
            }
        }

        if (jt < 7) { cp_wait<1>(); } else { cp_wait<0>(); }  // V(jt) ready
        __syncthreads();                          // sync3: P staged + V visible

        // ---- O += P @ hv^T (1x tf32 raw-bit operands, K=128) ----
#pragma unroll
        for (int kk = 0; kk < 16; kk++) {
            uint32_t aP[2][4], bV[4][2];
#pragma unroll
            for (int mf2 = 0; mf2 < 2; mf2++)
                ldsm4(aP[mf2], uP + a_lmP + (uint32_t)(mf2 * 16 * 528) + (uint32_t)(kk * 32));
#pragma unroll
            for (int nfp = 0; nfp < 2; nfp++) {
                uint32_t raw[4];
                ldsm4(raw, uV + b_lmV + (uint32_t)(nfp * 16 * 528) + (uint32_t)(kk * 32));
#pragma unroll
                for (int r = 0; r < 4; r++)
                    bV[2 * nfp + (r >> 1)][r & 1] = raw[r];
            }
#pragma unroll
            for (int mf2 = 0; mf2 < 2; mf2++)
#pragma unroll
                for (int nf2 = 0; nf2 < 4; nf2++)
                    mma8(oacc[mf2][nf2], aP[mf2], bV[nf2]);
        }
        __syncthreads();                          // sync4: V reads done

        if (jt < 7) {                             // prefetch V(jt+1)
            const float* Vn = Vg + (size_t)(j0 + 128);
#pragma unroll
            for (int s = tid; s < 2048; s += 256) { int r = s >> 5, c = s & 31;
                cpasync16(uV + (uint32_t)(r * 528 + c * 16), Vn + (size_t)r * 4096 + c * 4); }
            cp_commit();
        }
    }

    // ---- normalize + write cat ----
#pragma unroll
    for (int mf2 = 0; mf2 < 2; mf2++) {
        int r1 = wm2 * 32 + mf2 * 16 + g, r2 = r1 + 8;
        float inv1 = 1.0f / s_row[r1];
        float inv2 = 1.0f / s_row[r2];
#pragma unroll
        for (int nf2 = 0; nf2 < 4; nf2++) {
            int oc = wn2 * 32 + nf2 * 8 + 2 * t4;
            float* d1 = cat + (size_t)(zb * 1024 + i0 + r1) * 1024 + zh * 64 + oc;
            float* d2 = cat + (size_t)(zb * 1024 + i0 + r2) * 1024 + zh * 64 + oc;
            *(float2*)d1 = make_float2(oacc[mf2][nf2][0] * inv1, oacc[mf2][nf2][1] * inv1);
            *(float2*)d2 = make_float2(oacc[mf2][nf2][2] * inv2, oacc[mf2][nf2][3] * inv2);
        }
    }
}

// ---------------- relative positional embedding table (sincos pairs) ----------------
__global__ void compute_r_kernel(float* __restrict__ r) {
    int idx = blockIdx.x * blockDim.x + threadIdx.x;
    if (idx >= Pv * 512) return;
    int p    = idx >> 9;
    int half = idx & 511;
    float freq = 1.0f / powf(10000.0f, (float)(2 * half) / (float)Dv);
    float ang  = (float)(Lv - p) * freq;
    float s, c;
    sincosf(ang, &s, &c);
    *(float2*)(r + (size_t)p * 1024 + half * 2) = make_float2(s * 102.4f, c * 102.4f);
}

// ---------------- block reduction ----------------
__device__ __forceinline__ float blk_reduce(float v, float* sbuf, bool is_max) {
#pragma unroll
    for (int o = 16; o; o >>= 1) {
        float other = __shfl_xor_sync(0xffffffffu, v, o);
        v = is_max ? fmaxf(v, other) : (v + other);
    }
    int warp = threadIdx.x >> 5, lane = threadIdx.x & 31;
    if (lane == 0) sbuf[warp] = v;
    __syncthreads();
    if (threadIdx.x < 32) {
        float x = (threadIdx.x < 8) ? sbuf[threadIdx.x] : (is_max ? -3.402823466e38f : 0.f);
#pragma unroll
        for (int o = 4; o; o >>= 1) {
            float other = __shfl_xor_sync(0xffffffffu, x, o);
            x = is_max ? fmaxf(x, other) : (x + other);
        }
        if (threadIdx.x == 0) sbuf[0] = x;
    }
    __syncthreads();
    float r = sbuf[0];
    __syncthreads();
    return r;
}

// ---------------- LayerNorm (unbiased std, eps on std), in place ----------------
__global__ void ln_kernel(float* __restrict__ X,
                          const float* __restrict__ scale,
                          const float* __restrict__ offset) {
    __shared__ float sbuf[8];
    float* x = X + (size_t)blockIdx.x * 1024;
    int tid = threadIdx.x;
    float v[4];
#pragma unroll
    for (int t = 0; t < 4; t++) v[t] = x[t * 256 + tid];
    float sum = v[0] + v[1] + v[2] + v[3];
    sum = blk_reduce(sum, sbuf, false);
    float mean = sum * (1.0f / 1024.0f);
    float ss = 0.f;
#pragma unroll
    for (int t = 0; t < 4; t++) { float d = v[t] - mean; ss += d * d; }
    ss = blk_reduce(ss, sbuf, false);
    float stdv = sqrtf(ss * (1.0f / 1023.0f));
    float inv  = 1.0f / (stdv + 1e-9f);
#pragma unroll
    for (int t = 0; t < 4; t++) {
        int n = t * 256 + tid;
        x[n] = scale[n] * (v[t] - mean) * inv + offset[n];
    }
}

// ---------------- launch ----------------
extern "C" void kernel_launch(void* const* d_in, const int* in_sizes, int n_in,
                              void* d_out, int out_size) {
    (void)in_sizes; (void)n_in; (void)out_size;
    const float* q        = (const float*)d_in[0];
    const float* k        = (const float*)d_in[1];
    const float* v        = (const float*)d_in[2];
    const float* Wq       = (const float*)d_in[3];
    const float* Wk       = (const float*)d_in[4];
    const float* Wv       = (const float*)d_in[5];
    const float* Wr       = (const float*)d_in[6];
    const float* u_w      = (const float*)d_in[7];
    const float* v_w      = (const float*)d_in[8];
    const float* w_proj   = (const float*)d_in[9];
    const float* ln_scale = (const float*)d_in[10];
    const float* ln_off   = (const float*)d_in[11];
    float* out = (float*)d_out;

    float *p_r, *p_hqu, *p_hqv, *p_hk, *p_hvT, *p_hr, *p_pos, *p_cat;
    cudaGetSymbolAddress((void**)&p_r,   g_r);
    cudaGetSymbolAddress((void**)&p_hqu, g_hqu);
    cudaGetSymbolAddress((void**)&p_hqv, g_hqv);
    cudaGetSymbolAddress((void**)&p_hk,  g_hk);
    cudaGetSymbolAddress((void**)&p_hvT, g_hvT);
    cudaGetSymbolAddress((void**)&p_hr,  g_hr);
    cudaGetSymbolAddress((void**)&p_pos, g_pos);
    cudaGetSymbolAddress((void**)&p_cat, g_cat);

    const int SM128 = 3 * (128 * 36 + 128 * 36) * 4;  // 110592 (3-stage)
    const int SMFL  = 52864 * 4;                      // 211456
    cudaFuncSetAttribute(gemm_mma<128,1,3>, cudaFuncAttributeMaxDynamicSharedMemorySize, SM128);
    cudaFuncSetAttribute(gemm_mma<128,0,3>, cudaFuncAttributeMaxDynamicSharedMemorySize, SM128);
    cudaFuncSetAttribute(gemm_mma<128,0,1>, cudaFuncAttributeMaxDynamicSharedMemorySize, SM128);
    cudaFuncSetAttribute(gemm_mma<128,2,1>, cudaFuncAttributeMaxDynamicSharedMemorySize, SM128);
    cudaFuncSetAttribute(gemm_mma<128,3,1>, cudaFuncAttributeMaxDynamicSharedMemorySize, SM128);
    cudaFuncSetAttribute(flash_kernel,      cudaFuncAttributeMaxDynamicSharedMemorySize, SMFL);

    compute_r_kernel<<<(Pv * 512 + 255) / 256, 256>>>(p_r);

    // q-proj (full 3xTF32 — hqv feeds the large position term)
    gemm_mma<128,1,3><<<dim3(32, 8, 1), 256, SM128>>>(
        q, 1024, 0, 0, Wq, 1024, 0, 0,
        p_hqu, p_hqv, 1024, 0, 0, nullptr, u_w, v_w, 1024, 0);
    // k-proj (1x raw — content term only, 50x looser tolerance)
    gemm_mma<128,0,1><<<dim3(32, 8, 1), 256, SM128>>>(
        k, 1024, 0, 0, Wk, 1024, 0, 0,
        p_hk, nullptr, 1024, 0, 0, nullptr, nullptr, nullptr, 1024, 0);
    // v-proj (1x raw, transposed write -> hvT)
    gemm_mma<128,2,1><<<dim3(32, 8, 1), 256, SM128>>>(
        v, 1024, 0, 0, Wv, 1024, 0, 0,
        p_hvT, nullptr, 4096, 0, 0, nullptr, nullptr, nullptr, 1024, 0);
    // r-proj (full 3xTF32 — logit-critical)
    gemm_mma<128,0,3><<<dim3(16, 8, 1), 256, SM128>>>(
        p_r, 1024, 0, 0, Wr, 1024, 0, 0,
        p_hr, nullptr, 1024, 0, 0, nullptr, nullptr, nullptr, 1024, 0);

    // position scores (full 3xTF32, banded coalesced write — logit-critical)
    gemm_mma<128,0,3><<<dim3(8, 9, 64), 256, SM128>>>(
        p_hqv, 1024, 1048576LL, 64LL, p_hr, 1024, 0LL, 64LL,
        p_pos, nullptr, 2048, 33554432LL, 2097152LL, nullptr, nullptr, nullptr, 64, 1);

    // flash: content (X2) + shift + softmax + P@V -> cat
    flash_kernel<<<dim3(8, 64), 256, SMFL>>>(p_hqu, p_hk, p_hvT, p_pos, p_cat);

    // output projection + residual (1x raw)
    gemm_mma<128,3,1><<<dim3(32, 8, 1), 256, SM128>>>(
        p_cat, 1024, 0, 0, w_proj, 1024, 0, 0,
        out, nullptr, 1024, 0, 0, q, nullptr, nullptr, 1024, 0);

    ln_kernel<<<MBL, 256>>>(out, ln_scale, ln_off);
}

// round 14
// speedup vs baseline: 1.2929x; 1.2929x over previous
#include <cuda_runtime.h>
#include <cstdint>
#include <math.h>

// Problem constants
#define Bv   4
#define Lv   1024
#define Dv   1024
#define Pv   2048
#define MBL  4096

// ---------------- scratch (device globals) ----------------
__device__ float g_r   [(size_t)Pv  * Dv];    // rel-pos table [P, D]
__device__ float g_hqu [(size_t)MBL * Dv];    // hq + u_w
__device__ float g_hqv [(size_t)MBL * Dv];    // hq + v_w
__device__ float g_hk  [(size_t)MBL * Dv];    // hk
__device__ float g_hvT [(size_t)Dv  * MBL];   // hv transposed: [H*64][B*L]
__device__ float g_hr  [(size_t)Pv  * Dv];    // hr [P][H*64]
__device__ float g_pos [(size_t)64 * Lv * Pv];// position scores (banded fill)
__device__ float g_cat [(size_t)MBL * Dv];    // concatenated heads

// ================= helpers =================
__device__ __forceinline__ uint32_t smem_u32(const void* p) {
    uint32_t a;
    asm("{ .reg .u64 t; cvta.to.shared.u64 t, %1; cvt.u32.u64 %0, t; }" : "=r"(a) : "l"(p));
    return a;
}
__device__ __forceinline__ void cpasync16(uint32_t dst, const float* src) {
    asm volatile("cp.async.cg.shared.global [%0], [%1], 16;" :: "r"(dst), "l"(src) : "memory");
}
__device__ __forceinline__ void cp_commit() { asm volatile("cp.async.commit_group;" ::: "memory"); }
template <int N> __device__ __forceinline__ void cp_wait() {
    asm volatile("cp.async.wait_group %0;" :: "n"(N) : "memory");
}
__device__ __forceinline__ uint32_t cvt_tf32(float x) {
    uint32_t r; asm("cvt.rna.tf32.f32 %0, %1;" : "=r"(r) : "f"(x)); return r;
}
__device__ __forceinline__ void mma8(float* c, const uint32_t* a, const uint32_t* b) {
    asm volatile("mma.sync.aligned.m16n8k8.row.col.f32.tf32.tf32.f32 "
        "{%0,%1,%2,%3}, {%4,%5,%6,%7}, {%8,%9}, {%0,%1,%2,%3};"
        : "+f"(c[0]), "+f"(c[1]), "+f"(c[2]), "+f"(c[3])
        : "r"(a[0]), "r"(a[1]), "r"(a[2]), "r"(a[3]), "r"(b[0]), "r"(b[1]));
}
__device__ __forceinline__ void ldsm4(uint32_t* r, uint32_t addr) {
    asm volatile("ldmatrix.sync.aligned.m8n8.x4.shared.b16 {%0,%1,%2,%3}, [%4];"
        : "=r"(r[0]), "=r"(r[1]), "=r"(r[2]), "=r"(r[3]) : "r"(addr));
}

// ================= generic tf32 warp-MMA GEMM (R9 dual-buffer form) =================
// C[z][m][n] = sum_k A[..m,k] * B[..n,k]; B always [n][k] rows in smem (NK).
// EPI: 0 plain, 1 dual write +uvec/+vvec, 2 transposed write via smem stage,
//      3 residual add.
// XM:  1 = raw truncation (128 regs -> 2 CTAs/SM); 3 = full 3xTF32 (logit-critical).
template <int N_TILE, int EPI, int XM>
__global__ void __launch_bounds__(256) gemm_mma(
    const float* __restrict__ A, int lda, long long a_bs, long long a_hs,
    const float* __restrict__ B, int ldb, long long b_bs, long long b_hs,
    float* __restrict__ C, float* __restrict__ C2, int ldc, long long c_bs, long long c_hs,
    const float* __restrict__ res, const float* __restrict__ uvec, const float* __restrict__ vvec,
    int K, int band)
{
    constexpr int WARPS_M = (N_TILE == 128) ? 2 : 4;
    constexpr int WM = 128 / WARPS_M;
    constexpr int WN = N_TILE / (8 / WARPS_M);
    constexpr int MF = WM / 16;
    constexpr int NF = WN / 8;
    constexpr int AS = 36;                 // smem row stride in floats (144B)
    constexpr int BS = 36;
    constexpr int A_FL = 128 * AS;
    constexpr int B_FL = N_TILE * BS;

    extern __shared__ float sh[];
    const uint32_t shu = smem_u32(sh);
    const uint32_t Au[2] = { shu, shu + (uint32_t)A_FL * 4 };
    const uint32_t Bu[2] = { shu + (uint32_t)(2 * A_FL) * 4, shu + (uint32_t)(2 * A_FL + B_FL) * 4 };

    const int tid = threadIdx.x;
    const int wid = tid >> 5;
    const int lane = tid & 31;
    const int g  = lane >> 2;
    const int t4 = lane & 3;
    const int wm = wid % WARPS_M;
    const int wn = wid / WARPS_M;

    const int z = blockIdx.z, zb = z >> 4, zh = z & 15;
    const int m0 = blockIdx.x * 128;
    const int n0 = blockIdx.y * N_TILE + (band ? (896 - m0) : 0);
    const float* Abase = A + (size_t)zb * a_bs + (size_t)zh * a_hs + (size_t)m0 * lda;
    const float* Bbase = B + (size_t)zb * b_bs + (size_t)zh * b_hs + (size_t)n0 * ldb;
    const size_t coff = (size_t)zb * c_bs + (size_t)zh * c_hs;

    const int lane7 = lane & 7;
    const uint32_t a_lm = ((uint32_t)(wm * WM + lane7 + (((lane >> 3) & 1) << 3)) * AS
                           + ((lane & 16) ? 4u : 0u)) * 4u;
    const uint32_t b_lm = ((uint32_t)(wn * WN + lane7 + ((lane & 16) ? 8u : 0u)) * BS
                           + ((lane & 8) ? 4u : 0u)) * 4u;

    auto load_chunk = [&](int k0, int buf) {
        uint32_t sA = Au[buf], sB = Bu[buf];
#pragma unroll
        for (int s = tid; s < 1024; s += 256) {
            int r = s >> 3, c = s & 7;
            cpasync16(sA + (uint32_t)(r * (AS * 4) + c * 16), Abase + (size_t)r * lda + k0 + c * 4);
        }
#pragma unroll
        for (int s = tid; s < N_TILE * 8; s += 256) {
            int r = s >> 3, c = s & 7;
            cpasync16(sB + (uint32_t)(r * (BS * 4) + c * 16), Bbase + (size_t)r * ldb + k0 + c * 4);
        }
        cp_commit();
    };

    float acc[MF][NF][4] = {};

    const int NK = K >> 5;
    load_chunk(0, 0);
    if (NK > 1) load_chunk(32, 1);

    for (int kt = 0; kt < NK; kt++) {
        if (kt + 1 < NK) cp_wait<1>(); else cp_wait<0>();
        __syncthreads();
        const uint32_t As_ = Au[kt & 1] + a_lm;
        const uint32_t Bs_ = Bu[kt & 1] + b_lm;
#pragma unroll
        for (int kk = 0; kk < 4; kk++) {
            uint32_t ah[MF][4], al[MF][4];
            uint32_t bh[NF][2], bl[NF][2];
#pragma unroll
            for (int mf = 0; mf < MF; mf++) {
                uint32_t raw[4];
                ldsm4(raw, As_ + (uint32_t)(mf * 16 * AS * 4) + (uint32_t)(kk * 32));
#pragma unroll
                for (int r = 0; r < 4; r++) {
                    if constexpr (XM >= 2) {
                        float x = __uint_as_float(raw[r]);
                        ah[mf][r] = cvt_tf32(x);
                        al[mf][r] = __float_as_uint(x - __uint_as_float(ah[mf][r]));
                    } else {
                        ah[mf][r] = raw[r];   // HW truncates f32 -> tf32
                    }
                }
            }
#pragma unroll
            for (int nfp = 0; nfp < NF / 2; nfp++) {
                uint32_t raw[4];
                ldsm4(raw, Bs_ + (uint32_t)(nfp * 16 * BS * 4) + (uint32_t)(kk * 32));
#pragma unroll
                for (int r = 0; r < 4; r++) {
                    int nf = 2 * nfp + (r >> 1), rr = r & 1;
                    if constexpr (XM == 3) {
                        float y = __uint_as_float(raw[r]);
                        bh[nf][rr] = cvt_tf32(y);
                        bl[nf][rr] = __float_as_uint(y - __uint_as_float(bh[nf][rr]));
                    } else {
                        bh[nf][rr] = raw[r];
                    }
                }
            }
#pragma unroll
            for (int mf = 0; mf < MF; mf++)
#pragma unroll
                for (int nf = 0; nf < NF; nf++) {
                    if constexpr (XM == 3) {
                        mma8(acc[mf][nf], al[mf], bh[nf]);
                        mma8(acc[mf][nf], ah[mf], bl[nf]);
                    }
                    mma8(acc[mf][nf], ah[mf], bh[nf]);
                }
        }
        __syncthreads();
        if (kt + 2 < NK) load_chunk((kt + 2) * 32, kt & 1);
    }

    // ---------------- epilogue ----------------
    if constexpr (EPI == 2) {
        float* st = sh;
#pragma unroll
        for (int mf = 0; mf < MF; mf++)
#pragma unroll
            for (int nf = 0; nf < NF; nf++) {
                const float* a = acc[mf][nf];
                int rl = wm * WM + mf * 16 + g;
                int cl = wn * WN + nf * 8 + 2 * t4;
                st[(size_t)cl * 132 + rl]           = a[0];
                st[(size_t)(cl + 1) * 132 + rl]     = a[1];
                st[(size_t)cl * 132 + rl + 8]       = a[2];
                st[(size_t)(cl + 1) * 132 + rl + 8] = a[3];
            }
        __syncthreads();
        for (int s = tid; s < 128 * 32; s += 256) {
            int dv = s >> 5, c4 = (s & 31) << 2;
            float4 val = *(float4*)&st[(size_t)dv * 132 + c4];
            *(float4*)(C + (size_t)(n0 + dv) * ldc + m0 + c4) = val;
        }
        return;
    }
#pragma unroll
    for (int mf = 0; mf < MF; mf++) {
#pragma unroll
        for (int nf = 0; nf < NF; nf++) {
            const float* a = acc[mf][nf];
            const int row = m0 + wm * WM + mf * 16 + g;
            const int col = n0 + wn * WN + nf * 8 + 2 * t4;
            if constexpr (EPI == 0) {
                *(float2*)(C + coff + (size_t)row * ldc + col)       = make_float2(a[0], a[1]);
                *(float2*)(C + coff + (size_t)(row + 8) * ldc + col) = make_float2(a[2], a[3]);
            } else if constexpr (EPI == 1) {
                const int bi = col & 63;
                const float u0 = uvec[bi], u1 = uvec[bi + 1];
                const float v0 = vvec[bi], v1 = vvec[bi + 1];
                const size_t o1 = coff + (size_t)row * ldc + col;
                const size_t o2 = coff + (size_t)(row + 8) * ldc + col;
                *(float2*)(C  + o1) = make_float2(a[0] + u0, a[1] + u1);
                *(float2*)(C  + o2) = make_float2(a[2] + u0, a[3] + u1);
                *(float2*)(C2 + o1) = make_float2(a[0] + v0, a[1] + v1);
                *(float2*)(C2 + o2) = make_float2(a[2] + v0, a[3] + v1);
            } else {  // EPI == 3
                const size_t o1 = (size_t)row * ldc + col;
                const size_t o2 = (size_t)(row + 8) * ldc + col;
                float2 r1 = *(const float2*)(res + o1);
                float2 r2 = *(const float2*)(res + o2);
                *(float2*)(C + o1) = make_float2(a[0] + r1.x, a[1] + r1.y);
                *(float2*)(C + o2) = make_float2(a[2] + r2.x, a[3] + r2.y);
            }
        }
    }
}

// ================= flash kernel (256 threads): content X1 MMA + shift + online softmax + P@V ===
// smem (floats): sQ@0 128x68 | sK@8704 128x68 | sV@17408 64x132 | sP@25856 128x132
//   stats@42752 (m,s,f 128 each + red 512 + red2 512); total 44160 floats
__global__ void __launch_bounds__(256, 1) flash_kernel(
    const float* __restrict__ hqu, const float* __restrict__ hk,
    const float* __restrict__ hvT, const float* __restrict__ pos,
    float* __restrict__ cat)
{
    extern __shared__ float sh[];
    float* sP    = sh + 25856;
    float* m_row = sh + 42752;
    float* s_row = m_row + 128;
    float* f_row = s_row + 128;
    float* red   = f_row + 128;
    float* red2  = red + 512;

    const uint32_t shu = smem_u32(sh);
    const uint32_t uQ   = shu;
    const uint32_t uK   = shu + 8704u * 4u;
    const uint32_t uV   = shu + 17408u * 4u;
    const uint32_t uP   = shu + 25856u * 4u;

    const int tid = threadIdx.x, wid = tid >> 5, lane = tid & 31;
    const int g = lane >> 2, t4 = lane & 3, lane7 = lane & 7;
    const int wm = wid >> 2, wn = wid & 3;     // S-MMA layout 2x4 (WM=64, WN=32)
    const int wm2 = wid & 3, wn2 = wid >> 2;   // O-MMA layout 4x2 (WM=32, WN=32)

    const int i0 = blockIdx.x * 128;
    const int z = blockIdx.y, zb = z >> 4, zh = z & 15;

    const float* Qg = hqu + (size_t)zb * 1048576 + (size_t)zh * 64 + (size_t)i0 * 1024;
    const float* Kg = hk  + (size_t)zb * 1048576 + (size_t)zh * 64;
    const float* Vg = hvT + (size_t)zb * 1024    + (size_t)zh * 262144;
    const float* Pg = pos + (size_t)zb * 33554432 + (size_t)zh * 2097152;

    for (int r = tid; r < 128; r += 256) { m_row[r] = -3.4e38f; s_row[r] = 0.f; }

    // preload: group1 = Q + K(0); group2 = V(0)
#pragma unroll
    for (int s = tid; s < 2048; s += 256) { int r = s >> 4, c = s & 15;
        cpasync16(uQ + (uint32_t)(r * 272 + c * 16), Qg + (size_t)r * 1024 + c * 4); }
#pragma unroll
    for (int s = tid; s < 2048; s += 256) { int r = s >> 4, c = s & 15;
        cpasync16(uK + (uint32_t)(r * 272 + c * 16), Kg + (size_t)r * 1024 + c * 4); }
    cp_commit();
#pragma unroll
    for (int s = tid; s < 2048; s += 256) { int r = s >> 5, c = s & 31;
        cpasync16(uV + (uint32_t)(r * 528 + c * 16), Vg + (size_t)r * 4096 + c * 4); }
    cp_commit();

    const uint32_t a_lmS = (uint32_t)(wm * 64 + lane7 + (((lane >> 3) & 1) << 3)) * 272u + ((lane & 16) ? 16u : 0u);
    const uint32_t b_lmS = (uint32_t)(wn * 32 + lane7 + ((lane & 16) ? 8 : 0)) * 272u + ((lane & 8) ? 16u : 0u);
    const uint32_t a_lmP = (uint32_t)(wm2 * 32 + lane7 + (((lane >> 3) & 1) << 3)) * 528u + ((lane & 16) ? 16u : 0u);
    const uint32_t b_lmV = (uint32_t)(wn2 * 32 + lane7 + ((lane & 16) ? 8 : 0)) * 528u + ((lane & 8) ? 16u : 0u);

    float oacc[2][4][4] = {};

    for (int jt = 0; jt < 8; jt++) {
        const int j0 = jt * 128;
        cp_wait<1>(); __syncthreads();           // Q + K(jt) ready

        // ---- S = hqu_tile @ hk_tile^T (X1 tf32 raw, K=64) ----
        float sacc[4][4][4] = {};
#pragma unroll
        for (int kk = 0; kk < 8; kk++) {
            uint32_t ah[4][4], bh[4][2];
#pragma unroll
            for (int mf = 0; mf < 4; mf++)
                ldsm4(ah[mf], uQ + a_lmS + (uint32_t)(mf * 16 * 272) + (uint32_t)(kk * 32));
#pragma unroll
            for (int nfp = 0; nfp < 2; nfp++) {
                uint32_t raw[4];
                ldsm4(raw, uK + b_lmS + (uint32_t)(nfp * 16 * 272) + (uint32_t)(kk * 32));
#pragma unroll
                for (int r = 0; r < 4; r++)
                    bh[2 * nfp + (r >> 1)][r & 1] = raw[r];
            }
#pragma unroll
            for (int mf = 0; mf < 4; mf++)
#pragma unroll
                for (int nf = 0; nf < 4; nf++)
                    mma8(sacc[mf][nf], ah[mf], bh[nf]);
        }

        // ---- logits = (S + pos[i][1024-i+j]) / 32 ----
#pragma unroll
        for (int mf = 0; mf < 4; mf++) {
            const int r1 = i0 + wm * 64 + mf * 16 + g;
            const int r2 = r1 + 8;
            const float* pr1 = Pg + (size_t)r1 * 2048 + (1024 - r1 + j0);
            const float* pr2 = Pg + (size_t)r2 * 2048 + (1024 - r2 + j0);
#pragma unroll
            for (int nf = 0; nf < 4; nf++) {
                const int cj = wn * 32 + nf * 8 + 2 * t4;
                sacc[mf][nf][0] = (sacc[mf][nf][0] + pr1[cj])     * 0.03125f;
                sacc[mf][nf][1] = (sacc[mf][nf][1] + pr1[cj + 1]) * 0.03125f;
                sacc[mf][nf][2] = (sacc[mf][nf][2] + pr2[cj])     * 0.03125f;
                sacc[mf][nf][3] = (sacc[mf][nf][3] + pr2[cj + 1]) * 0.03125f;
            }
        }

        // ---- row max (local -> quad -> smem partials) ----
        float m_prev[8], mloc[8];
#pragma unroll
        for (int mf = 0; mf < 4; mf++)
#pragma unroll
            for (int h = 0; h < 2; h++) {
                int idx = mf * 2 + h;
                float mv = -3.4e38f;
#pragma unroll
                for (int nf = 0; nf < 4; nf++)
                    mv = fmaxf(mv, fmaxf(sacc[mf][nf][2 * h], sacc[mf][nf][2 * h + 1]));
                mloc[idx] = mv;
                m_prev[idx] = m_row[wm * 64 + mf * 16 + h * 8 + g];
            }
#pragma unroll
        for (int idx = 0; idx < 8; idx++) {
            mloc[idx] = fmaxf(mloc[idx], __shfl_xor_sync(0xffffffffu, mloc[idx], 1));
            mloc[idx] = fmaxf(mloc[idx], __shfl_xor_sync(0xffffffffu, mloc[idx], 2));
        }
        if (t4 == 0) {
#pragma unroll
            for (int mf = 0; mf < 4; mf++)
#pragma unroll
                for (int h = 0; h < 2; h++)
                    red[(wm * 64 + mf * 16 + h * 8 + g) * 4 + wn] = mloc[mf * 2 + h];
        }
        __syncthreads();                          // sync1: K reads done too

        if (jt < 7) {                             // prefetch K(jt+1), overlaps softmax+PV
            const float* Kn = Kg + (size_t)(j0 + 128) * 1024;
#pragma unroll
            for (int s = tid; s < 2048; s += 256) { int r = s >> 4, c = s & 15;
                cpasync16(uK + (uint32_t)(r * 272 + c * 16), Kn + (size_t)r * 1024 + c * 4); }
            cp_commit();
        }

        // ---- m_new, P = exp(logit - m_new), row sums ----
        float mn[8], fr[8], sl[8];
#pragma unroll
        for (int mf = 0; mf < 4; mf++)
#pragma unroll
            for (int h = 0; h < 2; h++) {
                int idx = mf * 2 + h;
                int row = wm * 64 + mf * 16 + h * 8 + g;
                float mm = fmaxf(fmaxf(red[row * 4 + 0], red[row * 4 + 1]),
                                 fmaxf(red[row * 4 + 2], red[row * 4 + 3]));
                mm = fmaxf(mm, m_prev[idx]);
                mn[idx] = mm;
                fr[idx] = expf(m_prev[idx] - mm);
                float ss = 0.f;
#pragma unroll
                for (int nf = 0; nf < 4; nf++) {
                    float p0 = expf(sacc[mf][nf][2 * h]     - mm);
                    float p1 = expf(sacc[mf][nf][2 * h + 1] - mm);
                    sacc[mf][nf][2 * h] = p0; sacc[mf][nf][2 * h + 1] = p1;
                    ss += p0 + p1;
                }
                sl[idx] = ss;
            }
#pragma unroll
        for (int idx = 0; idx < 8; idx++) {
            sl[idx] += __shfl_xor_sync(0xffffffffu, sl[idx], 1);
            sl[idx] += __shfl_xor_sync(0xffffffffu, sl[idx], 2);
        }
        if (t4 == 0) {
#pragma unroll
            for (int mf = 0; mf < 4; mf++)
#pragma unroll
                for (int h = 0; h < 2; h++) {
                    int row = wm * 64 + mf * 16 + h * 8 + g;
                    red2[row * 4 + wn] = sl[mf * 2 + h];
                    if (wn == 0) { m_row[row] = mn[mf * 2 + h]; f_row[row] = fr[mf * 2 + h]; }
                }
        }
        __syncthreads();                          // sync2

        if (wn == 0 && t4 == 0) {
#pragma unroll
            for (int mf = 0; mf < 4; mf++)
#pragma unroll
                for (int h = 0; h < 2; h++) {
                    int row = wm * 64 + mf * 16 + h * 8 + g;
                    s_row[row] = s_row[row] * fr[mf * 2 + h]
                        + red2[row * 4 + 0] + red2[row * 4 + 1] + red2[row * 4 + 2] + red2[row * 4 + 3];
                }
        }

        // ---- rescale O by f ----
#pragma unroll
        for (int mf2 = 0; mf2 < 2; mf2++) {
            float f1 = f_row[wm2 * 32 + mf2 * 16 + g];
            float f2 = f_row[wm2 * 32 + mf2 * 16 + g + 8];
#pragma unroll
            for (int nf2 = 0; nf2 < 4; nf2++) {
                oacc[mf2][nf2][0] *= f1; oacc[mf2][nf2][1] *= f1;
                oacc[mf2][nf2][2] *= f2; oacc[mf2][nf2][3] *= f2;
            }
        }

        // ---- stage P ----
#pragma unroll
        for (int mf = 0; mf < 4; mf++) {
            int r1 = wm * 64 + mf * 16 + g, r2 = r1 + 8;
#pragma unroll
            for (int nf = 0; nf < 4; nf++) {
                int cj = wn * 32 + nf * 8 + 2 * t4;
                sP[r1 * 132 + cj]     = sacc[mf][nf][0];
                sP[r1 * 132 + cj + 1] = sacc[mf][nf][1];
                sP[r2 * 132 + cj]     = sacc[mf][nf][2];
                sP[r2 * 132 + cj + 1] = sacc[mf][nf][3];
            }
        }

        if (jt < 7) { cp_wait<1>(); } else { cp_wait<0>(); }  // V(jt) ready
        __syncthreads();                          // sync3: P staged + V visible

        // ---- O += P @ hv^T (1x tf32 raw-bit operands, K=128) ----
#pragma unroll
        for (int kk = 0; kk < 16; kk++) {
            uint32_t aP[2][4], bV[4][2];
#pragma unroll
            for (int mf2 = 0; mf2 < 2; mf2++)
                ldsm4(aP[mf2], uP + a_lmP + (uint32_t)(mf2 * 16 * 528) + (uint32_t)(kk * 32));
#pragma unroll
            for (int nfp = 0; nfp < 2; nfp++) {
                uint32_t raw[4];
                ldsm4(raw, uV + b_lmV + (uint32_t)(nfp * 16 * 528) + (uint32_t)(kk * 32));
#pragma unroll
                for (int r = 0; r < 4; r++)
                    bV[2 * nfp + (r >> 1)][r & 1] = raw[r];
            }
#pragma unroll
            for (int mf2 = 0; mf2 < 2; mf2++)
#pragma unroll
                for (int nf2 = 0; nf2 < 4; nf2++)
                    mma8(oacc[mf2][nf2], aP[mf2], bV[nf2]);
        }
        __syncthreads();                          // sync4: V reads done

        if (jt < 7) {                             // prefetch V(jt+1)
            const float* Vn = Vg + (size_t)(j0 + 128);
#pragma unroll
            for (int s = tid; s < 2048; s += 256) { int r = s >> 5, c = s & 31;
                cpasync16(uV + (uint32_t)(r * 528 + c * 16), Vn + (size_t)r * 4096 + c * 4); }
            cp_commit();
        }
    }

    // ---- normalize + write cat ----
#pragma unroll
    for (int mf2 = 0; mf2 < 2; mf2++) {
        int r1 = wm2 * 32 + mf2 * 16 + g, r2 = r1 + 8;
        float inv1 = 1.0f / s_row[r1];
        float inv2 = 1.0f / s_row[r2];
#pragma unroll
        for (int nf2 = 0; nf2 < 4; nf2++) {
            int oc = wn2 * 32 + nf2 * 8 + 2 * t4;
            float* d1 = cat + (size_t)(zb * 1024 + i0 + r1) * 1024 + zh * 64 + oc;
            float* d2 = cat + (size_t)(zb * 1024 + i0 + r2) * 1024 + zh * 64 + oc;
            *(float2*)d1 = make_float2(oacc[mf2][nf2][0] * inv1, oacc[mf2][nf2][1] * inv1);
            *(float2*)d2 = make_float2(oacc[mf2][nf2][2] * inv2, oacc[mf2][nf2][3] * inv2);
        }
    }
}

// ---------------- relative positional embedding table (sincos pairs) ----------------
__global__ void compute_r_kernel(float* __restrict__ r) {
    int idx = blockIdx.x * blockDim.x + threadIdx.x;
    if (idx >= Pv * 512) return;
    int p    = idx >> 9;
    int half = idx & 511;
    float freq = 1.0f / powf(10000.0f, (float)(2 * half) / (float)Dv);
    float ang  = (float)(Lv - p) * freq;
    float s, c;
    sincosf(ang, &s, &c);
    *(float2*)(r + (size_t)p * 1024 + half * 2) = make_float2(s * 102.4f, c * 102.4f);
}

// ---------------- block reduction ----------------
__device__ __forceinline__ float blk_reduce(float v, float* sbuf, bool is_max) {
#pragma unroll
    for (int o = 16; o; o >>= 1) {
        float other = __shfl_xor_sync(0xffffffffu, v, o);
        v = is_max ? fmaxf(v, other) : (v + other);
    }
    int warp = threadIdx.x >> 5, lane = threadIdx.x & 31;
    if (lane == 0) sbuf[warp] = v;
    __syncthreads();
    if (threadIdx.x < 32) {
        float x = (threadIdx.x < 8) ? sbuf[threadIdx.x] : (is_max ? -3.402823466e38f : 0.f);
#pragma unroll
        for (int o = 4; o; o >>= 1) {
            float other = __shfl_xor_sync(0xffffffffu, x, o);
            x = is_max ? fmaxf(x, other) : (x + other);
        }
        if (threadIdx.x == 0) sbuf[0] = x;
    }
    __syncthreads();
    float r = sbuf[0];
    __syncthreads();
    return r;
}

// ---------------- LayerNorm (unbiased std, eps on std), in place ----------------
__global__ void ln_kernel(float* __restrict__ X,
                          const float* __restrict__ scale,
                          const float* __restrict__ offset) {
    __shared__ float sbuf[8];
    float* x = X + (size_t)blockIdx.x * 1024;
    int tid = threadIdx.x;
    float v[4];
#pragma unroll
    for (int t = 0; t < 4; t++) v[t] = x[t * 256 + tid];
    float sum = v[0] + v[1] + v[2] + v[3];
    sum = blk_reduce(sum, sbuf, false);
    float mean = sum * (1.0f / 1024.0f);
    float ss = 0.f;
#pragma unroll
    for (int t = 0; t < 4; t++) { float d = v[t] - mean; ss += d * d; }
    ss = blk_reduce(ss, sbuf, false);
    float stdv = sqrtf(ss * (1.0f / 1023.0f));
    float inv  = 1.0f / (stdv + 1e-9f);
#pragma unroll
    for (int t = 0; t < 4; t++) {
        int n = t * 256 + tid;
        x[n] = scale[n] * (v[t] - mean) * inv + offset[n];
    }
}

// ---------------- launch ----------------
extern "C" void kernel_launch(void* const* d_in, const int* in_sizes, int n_in,
                              void* d_out, int out_size) {
    (void)in_sizes; (void)n_in; (void)out_size;
    const float* q        = (const float*)d_in[0];
    const float* k        = (const float*)d_in[1];
    const float* v        = (const float*)d_in[2];
    const float* Wq       = (const float*)d_in[3];
    const float* Wk       = (const float*)d_in[4];
    const float* Wv       = (const float*)d_in[5];
    const float* Wr       = (const float*)d_in[6];
    const float* u_w      = (const float*)d_in[7];
    const float* v_w      = (const float*)d_in[8];
    const float* w_proj   = (const float*)d_in[9];
    const float* ln_scale = (const float*)d_in[10];
    const float* ln_off   = (const float*)d_in[11];
    float* out = (float*)d_out;

    float *p_r, *p_hqu, *p_hqv, *p_hk, *p_hvT, *p_hr, *p_pos, *p_cat;
    cudaGetSymbolAddress((void**)&p_r,   g_r);
    cudaGetSymbolAddress((void**)&p_hqu, g_hqu);
    cudaGetSymbolAddress((void**)&p_hqv, g_hqv);
    cudaGetSymbolAddress((void**)&p_hk,  g_hk);
    cudaGetSymbolAddress((void**)&p_hvT, g_hvT);
    cudaGetSymbolAddress((void**)&p_hr,  g_hr);
    cudaGetSymbolAddress((void**)&p_pos, g_pos);
    cudaGetSymbolAddress((void**)&p_cat, g_cat);

    const int SM128 = (2 * 128 * 36 + 2 * 128 * 36) * 4;  // 73728 (2-stage)
    const int SMFL  = 44160 * 4;                          // 176640
    cudaFuncSetAttribute(gemm_mma<128,1,3>, cudaFuncAttributeMaxDynamicSharedMemorySize, SM128);
    cudaFuncSetAttribute(gemm_mma<128,0,3>, cudaFuncAttributeMaxDynamicSharedMemorySize, SM128);
    cudaFuncSetAttribute(gemm_mma<128,0,1>, cudaFuncAttributeMaxDynamicSharedMemorySize, SM128);
    cudaFuncSetAttribute(gemm_mma<128,2,1>, cudaFuncAttributeMaxDynamicSharedMemorySize, SM128);
    cudaFuncSetAttribute(gemm_mma<128,3,1>, cudaFuncAttributeMaxDynamicSharedMemorySize, SM128);
    cudaFuncSetAttribute(flash_kernel,      cudaFuncAttributeMaxDynamicSharedMemorySize, SMFL);

    compute_r_kernel<<<(Pv * 512 + 255) / 256, 256>>>(p_r);

    // q-proj (full 3xTF32 — hqv feeds the large position term)
    gemm_mma<128,1,3><<<dim3(32, 8, 1), 256, SM128>>>(
        q, 1024, 0, 0, Wq, 1024, 0, 0,
        p_hqu, p_hqv, 1024, 0, 0, nullptr, u_w, v_w, 1024, 0);
    // k-proj (1x raw — content term only, 50x looser tolerance)
    gemm_mma<128,0,1><<<dim3(32, 8, 1), 256, SM128>>>(
        k, 1024, 0, 0, Wk, 1024, 0, 0,
        p_hk, nullptr, 1024, 0, 0, nullptr, nullptr, nullptr, 1024, 0);
    // v-proj (1x raw, transposed write -> hvT)
    gemm_mma<128,2,1><<<dim3(32, 8, 1), 256, SM128>>>(
        v, 1024, 0, 0, Wv, 1024, 0, 0,
        p_hvT, nullptr, 4096, 0, 0, nullptr, nullptr, nullptr, 1024, 0);
    // r-proj (full 3xTF32 — logit-critical)
    gemm_mma<128,0,3><<<dim3(16, 8, 1), 256, SM128>>>(
        p_r, 1024, 0, 0, Wr, 1024, 0, 0,
        p_hr, nullptr, 1024, 0, 0, nullptr, nullptr, nullptr, 1024, 0);

    // position scores (full 3xTF32, banded coalesced write — logit-critical)
    gemm_mma<128,0,3><<<dim3(8, 9, 64), 256, SM128>>>(
        p_hqv, 1024, 1048576LL, 64LL, p_hr, 1024, 0LL, 64LL,
        p_pos, nullptr, 2048, 33554432LL, 2097152LL, nullptr, nullptr, nullptr, 64, 1);

    // flash: content (X1 raw) + shift + softmax + P@V -> cat
    flash_kernel<<<dim3(8, 64), 256, SMFL>>>(p_hqu, p_hk, p_hvT, p_pos, p_cat);

    // output projection + residual (1x raw)
    gemm_mma<128,3,1><<<dim3(32, 8, 1), 256, SM128>>>(
        p_cat, 1024, 0, 0, w_proj, 1024, 0, 0,
        out, nullptr, 1024, 0, 0, q, nullptr, nullptr, 1024, 0);

    ln_kernel<<<MBL, 256>>>(out, ln_scale, ln_off);
}